// round 12
// baseline (speedup 1.0000x reference)
#include <cuda_runtime.h>
#include <math.h>
#include <float.h>

// Problem constants (fixed by the dataset)
#define BB 1024
#define LL 81
#define HH 8
#define DD 64
#define UU 10
#define NSAMP 41
#define WS 9
#define QSTR 68
#define KSTR 68

#define NTHREADS 256

// Shared memory layout (floats) — bias padded to 292 to keep csum 8B-aligned:
//   Qs 5508 | Ks 5508 | Vs 5184 | bias 292 | pmx 168 | psm 168 | csum 128
//   topi 16 ints | rank_of 81 ints
#define BIAS_PAD 292
#define SM_FLOATS (81*QSTR + 81*KSTR + 81*DD + BIAS_PAD + 168 + 168 + 128)
#define SM_BYTES  (SM_FLOATS*4 + (16 + 81)*4)

__device__ __forceinline__ unsigned long long ffma2(unsigned long long a,
                                                    unsigned long long b,
                                                    unsigned long long c) {
    unsigned long long d;
    asm("fma.rn.f32x2 %0, %1, %2, %3;" : "=l"(d) : "l"(a), "l"(b), "l"(c));
    return d;
}
__device__ __forceinline__ float f2sum(unsigned long long a) {
    return __uint_as_float((unsigned)(a & 0xffffffffull)) +
           __uint_as_float((unsigned)(a >> 32));
}

__global__ __launch_bounds__(NTHREADS, 3)
void prob_attn_kernel(const float* __restrict__ q_in,
                      const float* __restrict__ k_in,
                      const float* __restrict__ v_in,
                      const float* __restrict__ bias_in,
                      float* __restrict__ out_ctx,
                      float* __restrict__ out_attn)
{
    extern __shared__ float sm[];
    float* Qs    = sm;
    float* Ks    = Qs + 81*QSTR;
    float* Vs    = Ks + 81*KSTR;
    float* biass = Vs + 81*DD;
    float* pmx   = biass + BIAS_PAD;   // [2][84]
    float* psm   = pmx + 168;          // [2][84]
    float* csum  = psm + 168;          // 8B aligned (even float offset)
    int*   topi  = (int*)(csum + 128);
    int*   rank_of = topi + 16;

    const int tid  = threadIdx.x;
    const int warp = tid >> 5;
    const int lane = tid & 31;

    const int blk = blockIdx.x;
    const int b = blk >> 3;
    const int h = blk & 7;

    const size_t base = ((size_t)b * LL * HH + h) * DD;
    const float* qb = q_in + base;
    const float* kb = k_in + base;
    const float* vb = v_in + base;

    // ---- Phase A: load tiles (coalesced float4), bias, init rank map ----
    for (int idx = tid; idx < LL * 16; idx += NTHREADS) {
        int row = idx >> 4;
        int vec = idx & 15;
        size_t goff = (size_t)row * (HH * DD) + vec * 4;
        float4 qv = *(const float4*)(qb + goff);
        float4 kv = *(const float4*)(kb + goff);
        float4 vv = *(const float4*)(vb + goff);
        *(float4*)(Qs + row*QSTR + vec*4) = qv;
        *(float4*)(Ks + row*KSTR + vec*4) = kv;
        *(float4*)(Vs + row*DD   + vec*4) = vv;
    }
    for (int i = tid; i < 289; i += NTHREADS) biass[i] = bias_in[i];
    if (tid < LL) rank_of[tid] = -1;
    __syncthreads();

    // ---- Phase B: register-resident Q streaming.
    //      6 warps = 3 q-groups (27 rows, lane = row) x 2 s-halves.
    //      Q row loaded ONCE into 64 regs; K rows broadcast via LDS
    //      (all lanes same address -> 1 wavefront per LDS.128). ----
    if (warp < 6) {
        const int qg = warp >> 1;            // 0,1,2
        const int sh = warp & 1;             // 0,1
        const bool active = (lane < 27);
        const int q = qg * 27 + (active ? lane : 0);   // inactive lanes broadcast row

        unsigned long long qr[32];
        {
            const ulonglong2* qp = (const ulonglong2*)(Qs + q * QSTR);
            #pragma unroll
            for (int i = 0; i < 16; i++) {
                ulonglong2 t = qp[i];
                qr[2*i]   = t.x;
                qr[2*i+1] = t.y;
            }
        }

        float mx = -FLT_MAX, smv = 0.0f;
        const int s_beg = sh * 21;
        const int s_end = sh ? NSAMP : 21;   // 0..20 / 21..40
        for (int s = s_beg; s < s_end; s++) {
            const ulonglong2* kp = (const ulonglong2*)(Ks + 2 * s * KSTR);
            unsigned long long a0 = 0ull, a1 = 0ull;
            #pragma unroll
            for (int i = 0; i < 16; i++) {
                ulonglong2 kv = kp[i];       // warp-broadcast
                a0 = ffma2(qr[2*i],   kv.x, a0);
                a1 = ffma2(qr[2*i+1], kv.y, a1);
            }
            float v = f2sum(a0) + f2sum(a1);
            mx = fmaxf(mx, v);
            smv += v;
        }
        if (active) {
            pmx[sh * 84 + q] = mx;
            psm[sh * 84 + q] = smv;
        }
    }
    __syncthreads();

    // ---- Phase C (warp 0): folded M-reduction (2 halves) + top-10.
    //      Warps 5-6 concurrently: cumsum chunk sums (float2). ----
    if (warp == 0) {
        float m0, m1, m2 = -FLT_MAX;
        m0 = fmaxf(pmx[lane], pmx[84 + lane])
           - (psm[lane] + psm[84 + lane]) * (1.0f / 81.0f);
        m1 = fmaxf(pmx[lane + 32], pmx[84 + lane + 32])
           - (psm[lane + 32] + psm[84 + lane + 32]) * (1.0f / 81.0f);
        if (lane + 64 < LL)
            m2 = fmaxf(pmx[lane + 64], pmx[84 + lane + 64])
               - (psm[lane + 64] + psm[84 + lane + 64]) * (1.0f / 81.0f);

        #pragma unroll
        for (int r = 0; r < UU; r++) {
            float bv = m0; int bi = lane;
            if (m1 > bv) { bv = m1; bi = lane + 32; }
            if (m2 > bv) { bv = m2; bi = lane + 64; }
            #pragma unroll
            for (int o = 16; o > 0; o >>= 1) {
                float ov = __shfl_xor_sync(0xffffffffu, bv, o);
                int   oi = __shfl_xor_sync(0xffffffffu, bi, o);
                if (ov > bv || (ov == bv && oi < bi)) { bv = ov; bi = oi; }
            }
            if (lane == 0) { topi[r] = bi; rank_of[bi] = r; }
            if (bi == lane)           m0 = -FLT_MAX;
            else if (bi == lane + 32) m1 = -FLT_MAX;
            else if (bi == lane + 64) m2 = -FLT_MAX;
        }
    } else if (warp == 5 || warp == 6) {
        const int c = warp - 5;          // chunk 0 or 1
        const int l0 = c * 27;
        float2 s = make_float2(0.0f, 0.0f);
        for (int l = l0; l < l0 + 27; l++) {
            float2 v = *(const float2*)(Vs + l * DD + 2 * lane);
            s.x += v.x; s.y += v.y;
        }
        *(float2*)(csum + c * 64 + 2 * lane) = s;
    }
    __syncthreads();

    // ---- Phase D (warps 0-4): 2 rows per warp (scores+softmax+PV+direct STG).
    //      Warps 5-7 concurrently: cumsum + store of the 71 non-selected rows. ----
    const float scale = 0.125f;
    if (warp < 5) {
        const int r0 = 2 * warp, r1 = r0 + 1;
        const int qi0 = topi[r0], qi1 = topi[r1];
        const float* q0p = Qs + qi0 * QSTR;
        const float* q1p = Qs + qi1 * QSTR;

        float sc[2][3];
        #pragma unroll
        for (int t = 0; t < 3; t++) {
            int k = lane + t * 32;
            const float* kr = Ks + (k < LL ? k : LL - 1) * KSTR;
            unsigned long long a0 = 0ull, a1 = 0ull;
            #pragma unroll 4
            for (int d = 0; d < DD; d += 4) {
                ulonglong2 kv = *(const ulonglong2*)(kr + d);
                ulonglong2 qa = *(const ulonglong2*)(q0p + d);
                ulonglong2 qc = *(const ulonglong2*)(q1p + d);
                a0 = ffma2(qa.x, kv.x, a0);
                a0 = ffma2(qa.y, kv.y, a0);
                a1 = ffma2(qc.x, kv.x, a1);
                a1 = ffma2(qc.y, kv.y, a1);
            }
            sc[0][t] = f2sum(a0);
            sc[1][t] = f2sum(a1);
        }

        #pragma unroll
        for (int p = 0; p < 2; p++) {
            const int r = r0 + p;
            const int ri = r / WS, rj = r % WS;   // bias row indexed by RANK (ref quirk)
            float mx = -FLT_MAX;
            #pragma unroll
            for (int t = 0; t < 3; t++) {
                int k = lane + t * 32;
                if (k < LL) {
                    int ki = k / WS, kj = k - ki * WS;
                    int bidx = (ri - ki + (WS - 1)) * (2 * WS - 1) + (rj - kj + (WS - 1));
                    sc[p][t] = (sc[p][t] + biass[bidx]) * scale;
                } else {
                    sc[p][t] = -FLT_MAX;
                }
                mx = fmaxf(mx, sc[p][t]);
            }
            #pragma unroll
            for (int o = 16; o > 0; o >>= 1)
                mx = fmaxf(mx, __shfl_xor_sync(0xffffffffu, mx, o));

            float sum = 0.0f;
            #pragma unroll
            for (int t = 0; t < 3; t++) {
                int k = lane + t * 32;
                sc[p][t] = (k < LL) ? __expf(sc[p][t] - mx) : 0.0f;
                sum += sc[p][t];
            }
            #pragma unroll
            for (int o = 16; o > 0; o >>= 1)
                sum += __shfl_xor_sync(0xffffffffu, sum, o);
            const float inv = 1.0f / sum;

            #pragma unroll
            for (int t = 0; t < 3; t++) sc[p][t] *= inv;

            if (out_attn) {
                float* ao = out_attn + (((size_t)b * HH + h) * UU + r) * LL;
                #pragma unroll
                for (int t = 0; t < 3; t++) {
                    int k = lane + t * 32;
                    if (k < LL) ao[k] = sc[p][t];
                }
            }
        }

        // PV for both rows: outer t unrolled, inner sl loop ROLLED (I$ footprint).
        float2 pa0 = make_float2(0.f, 0.f), pa1 = make_float2(0.f, 0.f);
        #pragma unroll
        for (int t = 0; t < 3; t++) {
            const int kmax = (t == 2) ? (LL - 64) : 32;
            const float* vbase = Vs + t * 32 * DD + 2 * lane;
            for (int sl = 0; sl < kmax; sl++) {
                float2 v = *(const float2*)(vbase + sl * DD);
                float w0 = __shfl_sync(0xffffffffu, sc[0][t], sl);
                float w1 = __shfl_sync(0xffffffffu, sc[1][t], sl);
                pa0.x += w0 * v.x; pa0.y += w0 * v.y;
                pa1.x += w1 * v.x; pa1.y += w1 * v.y;
            }
        }
        *(float2*)(out_ctx + base + (size_t)qi0 * (HH * DD) + 2 * lane) = pa0;
        *(float2*)(out_ctx + base + (size_t)qi1 * (HH * DD) + 2 * lane) = pa1;
    } else {
        // warps 5,6,7 -> chunks 0,1,2: cumsum + store non-selected rows (float2)
        const int c = warp - 5;
        float2 acc = make_float2(0.0f, 0.0f);
        if (c > 0) { float2 t = *(const float2*)(csum + 2 * lane);      acc.x += t.x; acc.y += t.y; }
        if (c > 1) { float2 t = *(const float2*)(csum + 64 + 2 * lane); acc.x += t.x; acc.y += t.y; }
        float* ob = out_ctx + base + 2 * lane;
        const int l0 = c * 27;
        for (int l = l0; l < l0 + 27; l++) {
            float2 v = *(const float2*)(Vs + l * DD + 2 * lane);
            acc.x += v.x; acc.y += v.y;
            if (rank_of[l] < 0) {
                *(float2*)(ob + (size_t)l * (HH * DD)) = acc;
            }
        }
    }
}

extern "C" void kernel_launch(void* const* d_in, const int* in_sizes, int n_in,
                              void* d_out, int out_size)
{
    const float* q    = (const float*)d_in[0];
    const float* k    = (const float*)d_in[1];
    const float* v    = (const float*)d_in[2];
    const float* bias = (const float*)d_in[3];
    float* out = (float*)d_out;

    const long long ctx_elems  = (long long)BB * LL * HH * DD;
    const long long attn_elems = (long long)BB * HH * UU * LL;
    float* attn_out = ((long long)out_size >= ctx_elems + attn_elems)
                        ? out + ctx_elems : (float*)0;

    cudaFuncSetAttribute(prob_attn_kernel,
                         cudaFuncAttributeMaxDynamicSharedMemorySize, SM_BYTES);
    prob_attn_kernel<<<BB * HH, NTHREADS, SM_BYTES>>>(q, k, v, bias, out, attn_out);
}

// round 13
// speedup vs baseline: 1.1423x; 1.1423x over previous
#include <cuda_runtime.h>
#include <math.h>
#include <float.h>

// Problem constants (fixed by the dataset)
#define BB 1024
#define LL 81
#define HH 8
#define DD 64
#define UU 10
#define NSAMP 41
#define WS 9
#define QSTR 68
#define KSTR 68

#define NTHREADS 256
#define NBLOCKS  444   // 148 SMs x 3 resident CTAs: persistent grid

// Shared memory layout (floats) — bias padded to 292 to keep csum 8B-aligned:
//   Qs 5508 | Ks 5508 | Vs 5184 | bias 292 | pmx 924 | psm 924 | csum 128
//   topi 16 ints | rank_of 81 ints
#define BIAS_PAD 292
#define SM_FLOATS (81*QSTR + 81*KSTR + 81*DD + BIAS_PAD + 924 + 924 + 128)
#define SM_BYTES  (SM_FLOATS*4 + (16 + 81)*4)

__device__ __forceinline__ unsigned long long ffma2(unsigned long long a,
                                                    unsigned long long b,
                                                    unsigned long long c) {
    unsigned long long d;
    asm("fma.rn.f32x2 %0, %1, %2, %3;" : "=l"(d) : "l"(a), "l"(b), "l"(c));
    return d;
}
__device__ __forceinline__ float f2sum(unsigned long long a) {
    return __uint_as_float((unsigned)(a & 0xffffffffull)) +
           __uint_as_float((unsigned)(a >> 32));
}

__global__ __launch_bounds__(NTHREADS, 3)
void prob_attn_kernel(const float* __restrict__ q_in,
                      const float* __restrict__ k_in,
                      const float* __restrict__ v_in,
                      const float* __restrict__ bias_in,
                      float* __restrict__ out_ctx,
                      float* __restrict__ out_attn)
{
    extern __shared__ float sm[];
    float* Qs    = sm;
    float* Ks    = Qs + 81*QSTR;
    float* Vs    = Ks + 81*KSTR;
    float* biass = Vs + 81*DD;
    float* pmx   = biass + BIAS_PAD;
    float* psm   = pmx + 924;
    float* csum  = psm + 924;          // even float offset -> 8B aligned
    int*   topi  = (int*)(csum + 128);
    int*   rank_of = topi + 16;

    const int tid  = threadIdx.x;
    const int warp = tid >> 5;
    const int lane = tid & 31;

    // bias is task-invariant: load once
    for (int i = tid; i < 289; i += NTHREADS) biass[i] = bias_in[i];

    for (int task = blockIdx.x; task < BB * HH; task += NBLOCKS) {

    const int b = task >> 3;
    const int h = task & 7;

    const size_t base = ((size_t)b * LL * HH + h) * DD;
    const float* qb = q_in + base;
    const float* kb = k_in + base;
    const float* vb = v_in + base;

    // ---- Phase A: load tiles (coalesced float4), init rank map ----
    for (int idx = tid; idx < LL * 16; idx += NTHREADS) {
        int row = idx >> 4;
        int vec = idx & 15;
        size_t goff = (size_t)row * (HH * DD) + vec * 4;
        float4 qv = *(const float4*)(qb + goff);
        float4 kv = *(const float4*)(kb + goff);
        float4 vv = *(const float4*)(vb + goff);
        *(float4*)(Qs + row*QSTR + vec*4) = qv;
        *(float4*)(Ks + row*KSTR + vec*4) = kv;
        *(float4*)(Vs + row*DD   + vec*4) = vv;
    }
    if (tid < LL) rank_of[tid] = -1;
    __syncthreads();

    // ---- Phase B: sampled scores, 4q x 4s per thread, packed f32x2 FMA.
    //      q rows interleaved stride 21; s interleaved stride 11.
    if (tid < 231) {
        const int st = tid / 21;        // 0..10
        const int qt = tid - st * 21;   // 0..20

        const float* Qr[4];
        const float* Kr[4];
        #pragma unroll
        for (int i = 0; i < 4; i++) {
            int q = qt + 21 * i; if (q > 80) q = 80;
            Qr[i] = Qs + q * QSTR;
        }
        #pragma unroll
        for (int j = 0; j < 4; j++) {
            int s = st + 11 * j; if (s > 40) s = 40;
            Kr[j] = Ks + (2 * s) * KSTR;
        }

        unsigned long long acc2[4][4];
        #pragma unroll
        for (int i = 0; i < 4; i++)
            #pragma unroll
            for (int j = 0; j < 4; j++) acc2[i][j] = 0ull;

        #pragma unroll 2
        for (int d = 0; d < DD; d += 4) {
            ulonglong2 qv[4], kv[4];
            #pragma unroll
            for (int i = 0; i < 4; i++) qv[i] = *(const ulonglong2*)(Qr[i] + d);
            #pragma unroll
            for (int j = 0; j < 4; j++) kv[j] = *(const ulonglong2*)(Kr[j] + d);
            #pragma unroll
            for (int i = 0; i < 4; i++)
                #pragma unroll
                for (int j = 0; j < 4; j++) {
                    acc2[i][j] = ffma2(qv[i].x, kv[j].x, acc2[i][j]);
                    acc2[i][j] = ffma2(qv[i].y, kv[j].y, acc2[i][j]);
                }
        }

        #pragma unroll
        for (int i = 0; i < 4; i++) {
            int q = qt + 21 * i;
            if (q < LL) {
                float mx = -FLT_MAX, smv = 0.0f;
                #pragma unroll
                for (int j = 0; j < 4; j++) {
                    if (st + 11 * j < NSAMP) {
                        float v = f2sum(acc2[i][j]);
                        mx = fmaxf(mx, v);
                        smv += v;
                    }
                }
                pmx[st * 84 + q] = mx;
                psm[st * 84 + q] = smv;
            }
        }
    }
    __syncthreads();

    // ---- Phase C (warp 0): folded M-reduction + top-10.
    //      Warps 5-6 concurrently: cumsum chunk sums (float2). ----
    if (warp == 0) {
        float m0, m1, m2 = -FLT_MAX;
        {
            float mx = -FLT_MAX, smv = 0.0f;
            #pragma unroll
            for (int st = 0; st < 11; st++) {
                mx = fmaxf(mx, pmx[st * 84 + lane]);
                smv += psm[st * 84 + lane];
            }
            m0 = mx - smv * (1.0f / 81.0f);
        }
        {
            float mx = -FLT_MAX, smv = 0.0f;
            #pragma unroll
            for (int st = 0; st < 11; st++) {
                mx = fmaxf(mx, pmx[st * 84 + lane + 32]);
                smv += psm[st * 84 + lane + 32];
            }
            m1 = mx - smv * (1.0f / 81.0f);
        }
        if (lane + 64 < LL) {
            float mx = -FLT_MAX, smv = 0.0f;
            #pragma unroll
            for (int st = 0; st < 11; st++) {
                mx = fmaxf(mx, pmx[st * 84 + lane + 64]);
                smv += psm[st * 84 + lane + 64];
            }
            m2 = mx - smv * (1.0f / 81.0f);
        }

        #pragma unroll
        for (int r = 0; r < UU; r++) {
            float bv = m0; int bi = lane;
            if (m1 > bv) { bv = m1; bi = lane + 32; }
            if (m2 > bv) { bv = m2; bi = lane + 64; }
            #pragma unroll
            for (int o = 16; o > 0; o >>= 1) {
                float ov = __shfl_xor_sync(0xffffffffu, bv, o);
                int   oi = __shfl_xor_sync(0xffffffffu, bi, o);
                if (ov > bv || (ov == bv && oi < bi)) { bv = ov; bi = oi; }
            }
            if (lane == 0) { topi[r] = bi; rank_of[bi] = r; }
            if (bi == lane)           m0 = -FLT_MAX;
            else if (bi == lane + 32) m1 = -FLT_MAX;
            else if (bi == lane + 64) m2 = -FLT_MAX;
        }
    } else if (warp == 5 || warp == 6) {
        const int c = warp - 5;          // chunk 0 or 1
        const int l0 = c * 27;
        float2 s = make_float2(0.0f, 0.0f);
        for (int l = l0; l < l0 + 27; l++) {
            float2 v = *(const float2*)(Vs + l * DD + 2 * lane);
            s.x += v.x; s.y += v.y;
        }
        *(float2*)(csum + c * 64 + 2 * lane) = s;
    }
    __syncthreads();

    // ---- Phase D (warps 0-4): 2 rows per warp (scores+softmax+PV+direct STG).
    //      Warps 5-7 concurrently: cumsum + store of the 71 non-selected rows. ----
    const float scale = 0.125f;
    if (warp < 5) {
        const int r0 = 2 * warp, r1 = r0 + 1;
        const int qi0 = topi[r0], qi1 = topi[r1];
        const float* q0p = Qs + qi0 * QSTR;
        const float* q1p = Qs + qi1 * QSTR;

        float sc[2][3];
        #pragma unroll
        for (int t = 0; t < 3; t++) {
            int k = lane + t * 32;
            const float* kr = Ks + (k < LL ? k : LL - 1) * KSTR;
            unsigned long long a0 = 0ull, a1 = 0ull;
            #pragma unroll 4
            for (int d = 0; d < DD; d += 4) {
                ulonglong2 kv = *(const ulonglong2*)(kr + d);
                ulonglong2 qa = *(const ulonglong2*)(q0p + d);
                ulonglong2 qc = *(const ulonglong2*)(q1p + d);
                a0 = ffma2(qa.x, kv.x, a0);
                a0 = ffma2(qa.y, kv.y, a0);
                a1 = ffma2(qc.x, kv.x, a1);
                a1 = ffma2(qc.y, kv.y, a1);
            }
            sc[0][t] = f2sum(a0);
            sc[1][t] = f2sum(a1);
        }

        #pragma unroll
        for (int p = 0; p < 2; p++) {
            const int r = r0 + p;
            const int ri = r / WS, rj = r % WS;   // bias row indexed by RANK (ref quirk)
            float mx = -FLT_MAX;
            #pragma unroll
            for (int t = 0; t < 3; t++) {
                int k = lane + t * 32;
                if (k < LL) {
                    int ki = k / WS, kj = k - ki * WS;
                    int bidx = (ri - ki + (WS - 1)) * (2 * WS - 1) + (rj - kj + (WS - 1));
                    sc[p][t] = (sc[p][t] + biass[bidx]) * scale;
                } else {
                    sc[p][t] = -FLT_MAX;
                }
                mx = fmaxf(mx, sc[p][t]);
            }
            #pragma unroll
            for (int o = 16; o > 0; o >>= 1)
                mx = fmaxf(mx, __shfl_xor_sync(0xffffffffu, mx, o));

            float sum = 0.0f;
            #pragma unroll
            for (int t = 0; t < 3; t++) {
                int k = lane + t * 32;
                sc[p][t] = (k < LL) ? __expf(sc[p][t] - mx) : 0.0f;
                sum += sc[p][t];
            }
            #pragma unroll
            for (int o = 16; o > 0; o >>= 1)
                sum += __shfl_xor_sync(0xffffffffu, sum, o);
            const float inv = 1.0f / sum;

            #pragma unroll
            for (int t = 0; t < 3; t++) sc[p][t] *= inv;

            if (out_attn) {
                float* ao = out_attn + (((size_t)b * HH + h) * UU + r) * LL;
                #pragma unroll
                for (int t = 0; t < 3; t++) {
                    int k = lane + t * 32;
                    if (k < LL) ao[k] = sc[p][t];
                }
            }
        }

        // PV for both rows: outer t unrolled, inner sl loop ROLLED (I$ footprint).
        float2 pa0 = make_float2(0.f, 0.f), pa1 = make_float2(0.f, 0.f);
        #pragma unroll
        for (int t = 0; t < 3; t++) {
            const int kmax = (t == 2) ? (LL - 64) : 32;
            const float* vbase = Vs + t * 32 * DD + 2 * lane;
            for (int sl = 0; sl < kmax; sl++) {
                float2 v = *(const float2*)(vbase + sl * DD);
                float w0 = __shfl_sync(0xffffffffu, sc[0][t], sl);
                float w1 = __shfl_sync(0xffffffffu, sc[1][t], sl);
                pa0.x += w0 * v.x; pa0.y += w0 * v.y;
                pa1.x += w1 * v.x; pa1.y += w1 * v.y;
            }
        }
        *(float2*)(out_ctx + base + (size_t)qi0 * (HH * DD) + 2 * lane) = pa0;
        *(float2*)(out_ctx + base + (size_t)qi1 * (HH * DD) + 2 * lane) = pa1;
    } else {
        // warps 5,6,7 -> chunks 0,1,2: cumsum + store non-selected rows (float2)
        const int c = warp - 5;
        float2 acc = make_float2(0.0f, 0.0f);
        if (c > 0) { float2 t = *(const float2*)(csum + 2 * lane);      acc.x += t.x; acc.y += t.y; }
        if (c > 1) { float2 t = *(const float2*)(csum + 64 + 2 * lane); acc.x += t.x; acc.y += t.y; }
        float* ob = out_ctx + base + 2 * lane;
        const int l0 = c * 27;
        for (int l = l0; l < l0 + 27; l++) {
            float2 v = *(const float2*)(Vs + l * DD + 2 * lane);
            acc.x += v.x; acc.y += v.y;
            if (rank_of[l] < 0) {
                *(float2*)(ob + (size_t)l * (HH * DD)) = acc;
            }
        }
    }
    __syncthreads();   // protect tile buffers before next task's phase A

    } // task loop
}

extern "C" void kernel_launch(void* const* d_in, const int* in_sizes, int n_in,
                              void* d_out, int out_size)
{
    const float* q    = (const float*)d_in[0];
    const float* k    = (const float*)d_in[1];
    const float* v    = (const float*)d_in[2];
    const float* bias = (const float*)d_in[3];
    float* out = (float*)d_out;

    const long long ctx_elems  = (long long)BB * LL * HH * DD;
    const long long attn_elems = (long long)BB * HH * UU * LL;
    float* attn_out = ((long long)out_size >= ctx_elems + attn_elems)
                        ? out + ctx_elems : (float*)0;

    cudaFuncSetAttribute(prob_attn_kernel,
                         cudaFuncAttributeMaxDynamicSharedMemorySize, SM_BYTES);
    prob_attn_kernel<<<NBLOCKS, NTHREADS, SM_BYTES>>>(q, k, v, bias, out, attn_out);
}

// round 14
// speedup vs baseline: 1.1727x; 1.0266x over previous
#include <cuda_runtime.h>
#include <math.h>
#include <float.h>

// Problem constants (fixed by the dataset)
#define BB 1024
#define LL 81
#define HH 8
#define DD 64
#define UU 10
#define NSAMP 41
#define WS 9
#define QSTR 68
#define KSTR 68

#define NT1 256

// Kernel-1 shared memory (floats): Qs 5508 | Ks 5508 | bias 292 | pmx 924 | psm 924
// + topi 16 ints
#define BIAS_PAD 292
#define SM1_FLOATS (81*QSTR + 81*KSTR + BIAS_PAD + 924 + 924)
#define SM1_BYTES  (SM1_FLOATS*4 + 16*4)

// Inter-kernel scratch (static device arrays — allowed)
__device__ int   g_topi[BB * HH * UU];
__device__ float g_attn[(size_t)BB * HH * UU * LL];

__device__ __forceinline__ unsigned long long ffma2(unsigned long long a,
                                                    unsigned long long b,
                                                    unsigned long long c) {
    unsigned long long d;
    asm("fma.rn.f32x2 %0, %1, %2, %3;" : "=l"(d) : "l"(a), "l"(b), "l"(c));
    return d;
}
__device__ __forceinline__ float f2sum(unsigned long long a) {
    return __uint_as_float((unsigned)(a & 0xffffffffull)) +
           __uint_as_float((unsigned)(a >> 32));
}

// ============================================================================
// Kernel 1: sampled sparsity measure, top-10 selection, scores+softmax.
// Writes attn (to out_attn or scratch) and topi (scratch). No V work.
// ============================================================================
__global__ __launch_bounds__(NT1, 4)
void pa_select_kernel(const float* __restrict__ q_in,
                      const float* __restrict__ k_in,
                      const float* __restrict__ bias_in,
                      float* __restrict__ out_attn)
{
    extern __shared__ float sm[];
    float* Qs    = sm;
    float* Ks    = Qs + 81*QSTR;
    float* biass = Ks + 81*KSTR;
    float* pmx   = biass + BIAS_PAD;
    float* psm   = pmx + 924;
    int*   topi  = (int*)(psm + 924);

    const int tid  = threadIdx.x;
    const int warp = tid >> 5;
    const int lane = tid & 31;

    const int task = blockIdx.x;
    const int b = task >> 3;
    const int h = task & 7;

    const size_t base = ((size_t)b * LL * HH + h) * DD;
    const float* qb = q_in + base;
    const float* kb = k_in + base;

    // ---- Phase A: load Q/K tiles (coalesced float4) + bias ----
    for (int idx = tid; idx < LL * 16; idx += NT1) {
        int row = idx >> 4;
        int vec = idx & 15;
        size_t goff = (size_t)row * (HH * DD) + vec * 4;
        float4 qv = *(const float4*)(qb + goff);
        float4 kv = *(const float4*)(kb + goff);
        *(float4*)(Qs + row*QSTR + vec*4) = qv;
        *(float4*)(Ks + row*KSTR + vec*4) = kv;
    }
    for (int i = tid; i < 289; i += NT1) biass[i] = bias_in[i];
    __syncthreads();

    // ---- Phase B: sampled scores, 4q x 4s per thread, packed f32x2 FMA.
    //      kv loaded per-j to keep live registers under the 64-reg cap. ----
    if (tid < 231) {
        const int st = tid / 21;        // 0..10
        const int qt = tid - st * 21;   // 0..20

        const float* Qr[4];
        const float* Kr[4];
        #pragma unroll
        for (int i = 0; i < 4; i++) {
            int q = qt + 21 * i; if (q > 80) q = 80;
            Qr[i] = Qs + q * QSTR;
        }
        #pragma unroll
        for (int j = 0; j < 4; j++) {
            int s = st + 11 * j; if (s > 40) s = 40;
            Kr[j] = Ks + (2 * s) * KSTR;
        }

        unsigned long long acc2[4][4];
        #pragma unroll
        for (int i = 0; i < 4; i++)
            #pragma unroll
            for (int j = 0; j < 4; j++) acc2[i][j] = 0ull;

        #pragma unroll 2
        for (int d = 0; d < DD; d += 4) {
            ulonglong2 qv[4];
            #pragma unroll
            for (int i = 0; i < 4; i++) qv[i] = *(const ulonglong2*)(Qr[i] + d);
            #pragma unroll
            for (int j = 0; j < 4; j++) {
                ulonglong2 kv = *(const ulonglong2*)(Kr[j] + d);
                #pragma unroll
                for (int i = 0; i < 4; i++) {
                    acc2[i][j] = ffma2(qv[i].x, kv.x, acc2[i][j]);
                    acc2[i][j] = ffma2(qv[i].y, kv.y, acc2[i][j]);
                }
            }
        }

        #pragma unroll
        for (int i = 0; i < 4; i++) {
            int q = qt + 21 * i;
            if (q < LL) {
                float mx = -FLT_MAX, smv = 0.0f;
                #pragma unroll
                for (int j = 0; j < 4; j++) {
                    if (st + 11 * j < NSAMP) {
                        float v = f2sum(acc2[i][j]);
                        mx = fmaxf(mx, v);
                        smv += v;
                    }
                }
                pmx[st * 84 + q] = mx;
                psm[st * 84 + q] = smv;
            }
        }
    }
    __syncthreads();

    // ---- Phase C (warp 0): folded M-reduction + top-10 (tie -> lower index) ----
    if (warp == 0) {
        float m0, m1, m2 = -FLT_MAX;
        {
            float mx = -FLT_MAX, smv = 0.0f;
            #pragma unroll
            for (int st = 0; st < 11; st++) {
                mx = fmaxf(mx, pmx[st * 84 + lane]);
                smv += psm[st * 84 + lane];
            }
            m0 = mx - smv * (1.0f / 81.0f);
        }
        {
            float mx = -FLT_MAX, smv = 0.0f;
            #pragma unroll
            for (int st = 0; st < 11; st++) {
                mx = fmaxf(mx, pmx[st * 84 + lane + 32]);
                smv += psm[st * 84 + lane + 32];
            }
            m1 = mx - smv * (1.0f / 81.0f);
        }
        if (lane + 64 < LL) {
            float mx = -FLT_MAX, smv = 0.0f;
            #pragma unroll
            for (int st = 0; st < 11; st++) {
                mx = fmaxf(mx, pmx[st * 84 + lane + 64]);
                smv += psm[st * 84 + lane + 64];
            }
            m2 = mx - smv * (1.0f / 81.0f);
        }

        #pragma unroll
        for (int r = 0; r < UU; r++) {
            float bv = m0; int bi = lane;
            if (m1 > bv) { bv = m1; bi = lane + 32; }
            if (m2 > bv) { bv = m2; bi = lane + 64; }
            #pragma unroll
            for (int o = 16; o > 0; o >>= 1) {
                float ov = __shfl_xor_sync(0xffffffffu, bv, o);
                int   oi = __shfl_xor_sync(0xffffffffu, bi, o);
                if (ov > bv || (ov == bv && oi < bi)) { bv = ov; bi = oi; }
            }
            if (lane == 0) topi[r] = bi;
            if (bi == lane)           m0 = -FLT_MAX;
            else if (bi == lane + 32) m1 = -FLT_MAX;
            else if (bi == lane + 64) m2 = -FLT_MAX;
        }
        __syncwarp();
        if (lane < UU) g_topi[task * UU + lane] = topi[lane];
    }
    __syncthreads();

    // ---- Phase D (warps 0-4): 2 rows per warp — scores + softmax + attn out ----
    const float scale = 0.125f;
    if (warp < 5) {
        const int r0 = 2 * warp, r1 = r0 + 1;
        const float* q0p = Qs + topi[r0] * QSTR;
        const float* q1p = Qs + topi[r1] * QSTR;

        float sc[2][3];
        #pragma unroll
        for (int t = 0; t < 3; t++) {
            int k = lane + t * 32;
            const float* kr = Ks + (k < LL ? k : LL - 1) * KSTR;
            unsigned long long a0 = 0ull, a1 = 0ull;
            #pragma unroll 4
            for (int d = 0; d < DD; d += 4) {
                ulonglong2 kv = *(const ulonglong2*)(kr + d);
                ulonglong2 qa = *(const ulonglong2*)(q0p + d);
                ulonglong2 qc = *(const ulonglong2*)(q1p + d);
                a0 = ffma2(qa.x, kv.x, a0);
                a0 = ffma2(qa.y, kv.y, a0);
                a1 = ffma2(qc.x, kv.x, a1);
                a1 = ffma2(qc.y, kv.y, a1);
            }
            sc[0][t] = f2sum(a0);
            sc[1][t] = f2sum(a1);
        }

        float* ab = (out_attn ? out_attn : g_attn) + (size_t)task * UU * LL;

        #pragma unroll
        for (int p = 0; p < 2; p++) {
            const int r = r0 + p;
            const int ri = r / WS, rj = r % WS;   // bias row indexed by RANK (ref quirk)
            float mx = -FLT_MAX;
            #pragma unroll
            for (int t = 0; t < 3; t++) {
                int k = lane + t * 32;
                if (k < LL) {
                    int ki = k / WS, kj = k - ki * WS;
                    int bidx = (ri - ki + (WS - 1)) * (2 * WS - 1) + (rj - kj + (WS - 1));
                    sc[p][t] = (sc[p][t] + biass[bidx]) * scale;
                } else {
                    sc[p][t] = -FLT_MAX;
                }
                mx = fmaxf(mx, sc[p][t]);
            }
            #pragma unroll
            for (int o = 16; o > 0; o >>= 1)
                mx = fmaxf(mx, __shfl_xor_sync(0xffffffffu, mx, o));

            float sum = 0.0f;
            #pragma unroll
            for (int t = 0; t < 3; t++) {
                int k = lane + t * 32;
                sc[p][t] = (k < LL) ? __expf(sc[p][t] - mx) : 0.0f;
                sum += sc[p][t];
            }
            #pragma unroll
            for (int o = 16; o > 0; o >>= 1)
                sum += __shfl_xor_sync(0xffffffffu, sum, o);
            const float inv = 1.0f / sum;

            float* ao = ab + (size_t)r * LL;
            #pragma unroll
            for (int t = 0; t < 3; t++) {
                int k = lane + t * 32;
                if (k < LL) ao[k] = sc[p][t] * inv;
            }
        }
    }
}

// ============================================================================
// Kernel 2: per-(b,h) context = cumsum(V) with top rows replaced by attn @ V.
// 64 threads, thread = d. V streamed from gmem; attn broadcast from SMEM.
// ============================================================================
__global__ __launch_bounds__(64)
void pa_context_kernel(const float* __restrict__ v_in,
                       const float* __restrict__ attn_in,
                       float* __restrict__ out_ctx)
{
    __shared__ float attn_s[UU * LL];
    __shared__ int   topi_s[UU];
    __shared__ int   rank_s[LL];

    const int task = blockIdx.x;
    const int d = threadIdx.x;

    const float* ap = (attn_in ? attn_in : g_attn) + (size_t)task * UU * LL;
    for (int i = d; i < UU * LL; i += 64) attn_s[i] = ap[i];
    if (d < UU) topi_s[d] = g_topi[task * UU + d];
    for (int l = d; l < LL; l += 64) rank_s[l] = -1;
    __syncthreads();
    if (d < UU) rank_s[topi_s[d]] = d;
    __syncthreads();

    const int b = task >> 3;
    const int h = task & 7;
    const size_t base = ((size_t)b * LL * HH + h) * DD + d;
    const float* vb = v_in + base;
    float* ob = out_ctx + base;

    float upd[UU];
    #pragma unroll
    for (int r = 0; r < UU; r++) upd[r] = 0.0f;
    float cum = 0.0f;

    #pragma unroll 3
    for (int l = 0; l < LL; l++) {
        float v = __ldg(vb + (size_t)l * (HH * DD));
        cum += v;
        if (rank_s[l] < 0) ob[(size_t)l * (HH * DD)] = cum;
        #pragma unroll
        for (int r = 0; r < UU; r++) upd[r] += attn_s[r * LL + l] * v;
    }

    #pragma unroll
    for (int r = 0; r < UU; r++)
        ob[(size_t)topi_s[r] * (HH * DD)] = upd[r];
}

extern "C" void kernel_launch(void* const* d_in, const int* in_sizes, int n_in,
                              void* d_out, int out_size)
{
    const float* q    = (const float*)d_in[0];
    const float* k    = (const float*)d_in[1];
    const float* v    = (const float*)d_in[2];
    const float* bias = (const float*)d_in[3];
    float* out = (float*)d_out;

    const long long ctx_elems  = (long long)BB * LL * HH * DD;
    const long long attn_elems = (long long)BB * HH * UU * LL;
    float* attn_out = ((long long)out_size >= ctx_elems + attn_elems)
                        ? out + ctx_elems : (float*)0;

    cudaFuncSetAttribute(pa_select_kernel,
                         cudaFuncAttributeMaxDynamicSharedMemorySize, SM1_BYTES);
    pa_select_kernel<<<BB * HH, NT1, SM1_BYTES>>>(q, k, bias, attn_out);
    pa_context_kernel<<<BB * HH, 64>>>(v, attn_out, out);
}

// round 15
// speedup vs baseline: 1.1974x; 1.0210x over previous
#include <cuda_runtime.h>
#include <math.h>
#include <float.h>

// Problem constants (fixed by the dataset)
#define BB 1024
#define LL 81
#define HH 8
#define DD 64
#define UU 10
#define NSAMP 41
#define WS 9
#define QSTR 68
#define KSTR 68

#define NT1 256

// Kernel-1 shared memory (floats): Qs 5508 | Ks 5508 | bias 292 | pmx 924 | psm 924
// + topi 16 ints
#define BIAS_PAD 292
#define SM1_FLOATS (81*QSTR + 81*KSTR + BIAS_PAD + 924 + 924)
#define SM1_BYTES  (SM1_FLOATS*4 + 16*4)

// Inter-kernel scratch (static device arrays — allowed)
__device__ int   g_topi[BB * HH * UU];
__device__ float g_attn[(size_t)BB * HH * UU * LL];

__device__ __forceinline__ unsigned long long ffma2(unsigned long long a,
                                                    unsigned long long b,
                                                    unsigned long long c) {
    unsigned long long d;
    asm("fma.rn.f32x2 %0, %1, %2, %3;" : "=l"(d) : "l"(a), "l"(b), "l"(c));
    return d;
}
__device__ __forceinline__ float f2sum(unsigned long long a) {
    return __uint_as_float((unsigned)(a & 0xffffffffull)) +
           __uint_as_float((unsigned)(a >> 32));
}

// ============================================================================
// Kernel 1: sampled sparsity measure, top-10 selection, scores+softmax.
// Writes attn (to out_attn or scratch) and topi (scratch). No V work.
// ============================================================================
__global__ __launch_bounds__(NT1, 4)
void pa_select_kernel(const float* __restrict__ q_in,
                      const float* __restrict__ k_in,
                      const float* __restrict__ bias_in,
                      float* __restrict__ out_attn)
{
    extern __shared__ float sm[];
    float* Qs    = sm;
    float* Ks    = Qs + 81*QSTR;
    float* biass = Ks + 81*KSTR;
    float* pmx   = biass + BIAS_PAD;
    float* psm   = pmx + 924;
    int*   topi  = (int*)(psm + 924);

    const int tid  = threadIdx.x;
    const int warp = tid >> 5;
    const int lane = tid & 31;

    const int task = blockIdx.x;
    const int b = task >> 3;
    const int h = task & 7;

    const size_t base = ((size_t)b * LL * HH + h) * DD;
    const float* qb = q_in + base;
    const float* kb = k_in + base;

    // ---- Phase A: load Q/K tiles (coalesced float4) + bias ----
    for (int idx = tid; idx < LL * 16; idx += NT1) {
        int row = idx >> 4;
        int vec = idx & 15;
        size_t goff = (size_t)row * (HH * DD) + vec * 4;
        float4 qv = *(const float4*)(qb + goff);
        float4 kv = *(const float4*)(kb + goff);
        *(float4*)(Qs + row*QSTR + vec*4) = qv;
        *(float4*)(Ks + row*KSTR + vec*4) = kv;
    }
    for (int i = tid; i < 289; i += NT1) biass[i] = bias_in[i];
    __syncthreads();

    // ---- Phase B: sampled scores, 4q x 4s per thread, packed f32x2 FMA.
    //      kv loaded per-j to keep live registers under the 64-reg cap. ----
    if (tid < 231) {
        const int st = tid / 21;        // 0..10
        const int qt = tid - st * 21;   // 0..20

        const float* Qr[4];
        const float* Kr[4];
        #pragma unroll
        for (int i = 0; i < 4; i++) {
            int q = qt + 21 * i; if (q > 80) q = 80;
            Qr[i] = Qs + q * QSTR;
        }
        #pragma unroll
        for (int j = 0; j < 4; j++) {
            int s = st + 11 * j; if (s > 40) s = 40;
            Kr[j] = Ks + (2 * s) * KSTR;
        }

        unsigned long long acc2[4][4];
        #pragma unroll
        for (int i = 0; i < 4; i++)
            #pragma unroll
            for (int j = 0; j < 4; j++) acc2[i][j] = 0ull;

        #pragma unroll 2
        for (int d = 0; d < DD; d += 4) {
            ulonglong2 qv[4];
            #pragma unroll
            for (int i = 0; i < 4; i++) qv[i] = *(const ulonglong2*)(Qr[i] + d);
            #pragma unroll
            for (int j = 0; j < 4; j++) {
                ulonglong2 kv = *(const ulonglong2*)(Kr[j] + d);
                #pragma unroll
                for (int i = 0; i < 4; i++) {
                    acc2[i][j] = ffma2(qv[i].x, kv.x, acc2[i][j]);
                    acc2[i][j] = ffma2(qv[i].y, kv.y, acc2[i][j]);
                }
            }
        }

        #pragma unroll
        for (int i = 0; i < 4; i++) {
            int q = qt + 21 * i;
            if (q < LL) {
                float mx = -FLT_MAX, smv = 0.0f;
                #pragma unroll
                for (int j = 0; j < 4; j++) {
                    if (st + 11 * j < NSAMP) {
                        float v = f2sum(acc2[i][j]);
                        mx = fmaxf(mx, v);
                        smv += v;
                    }
                }
                pmx[st * 84 + q] = mx;
                psm[st * 84 + q] = smv;
            }
        }
    }
    __syncthreads();

    // ---- Phase C (warp 0): folded M-reduction + top-10 (tie -> lower index) ----
    if (warp == 0) {
        float m0, m1, m2 = -FLT_MAX;
        {
            float mx = -FLT_MAX, smv = 0.0f;
            #pragma unroll
            for (int st = 0; st < 11; st++) {
                mx = fmaxf(mx, pmx[st * 84 + lane]);
                smv += psm[st * 84 + lane];
            }
            m0 = mx - smv * (1.0f / 81.0f);
        }
        {
            float mx = -FLT_MAX, smv = 0.0f;
            #pragma unroll
            for (int st = 0; st < 11; st++) {
                mx = fmaxf(mx, pmx[st * 84 + lane + 32]);
                smv += psm[st * 84 + lane + 32];
            }
            m1 = mx - smv * (1.0f / 81.0f);
        }
        if (lane + 64 < LL) {
            float mx = -FLT_MAX, smv = 0.0f;
            #pragma unroll
            for (int st = 0; st < 11; st++) {
                mx = fmaxf(mx, pmx[st * 84 + lane + 64]);
                smv += psm[st * 84 + lane + 64];
            }
            m2 = mx - smv * (1.0f / 81.0f);
        }

        #pragma unroll
        for (int r = 0; r < UU; r++) {
            float bv = m0; int bi = lane;
            if (m1 > bv) { bv = m1; bi = lane + 32; }
            if (m2 > bv) { bv = m2; bi = lane + 64; }
            #pragma unroll
            for (int o = 16; o > 0; o >>= 1) {
                float ov = __shfl_xor_sync(0xffffffffu, bv, o);
                int   oi = __shfl_xor_sync(0xffffffffu, bi, o);
                if (ov > bv || (ov == bv && oi < bi)) { bv = ov; bi = oi; }
            }
            if (lane == 0) topi[r] = bi;
            if (bi == lane)           m0 = -FLT_MAX;
            else if (bi == lane + 32) m1 = -FLT_MAX;
            else if (bi == lane + 64) m2 = -FLT_MAX;
        }
        __syncwarp();
        if (lane < UU) g_topi[task * UU + lane] = topi[lane];
    }
    __syncthreads();

    // ---- Phase D (warps 0-4): 2 rows per warp — scores + softmax + attn out ----
    const float scale = 0.125f;
    if (warp < 5) {
        const int r0 = 2 * warp, r1 = r0 + 1;
        const float* q0p = Qs + topi[r0] * QSTR;
        const float* q1p = Qs + topi[r1] * QSTR;

        float sc[2][3];
        #pragma unroll
        for (int t = 0; t < 3; t++) {
            int k = lane + t * 32;
            const float* kr = Ks + (k < LL ? k : LL - 1) * KSTR;
            unsigned long long a0 = 0ull, a1 = 0ull;
            #pragma unroll 4
            for (int d = 0; d < DD; d += 4) {
                ulonglong2 kv = *(const ulonglong2*)(kr + d);
                ulonglong2 qa = *(const ulonglong2*)(q0p + d);
                ulonglong2 qc = *(const ulonglong2*)(q1p + d);
                a0 = ffma2(qa.x, kv.x, a0);
                a0 = ffma2(qa.y, kv.y, a0);
                a1 = ffma2(qc.x, kv.x, a1);
                a1 = ffma2(qc.y, kv.y, a1);
            }
            sc[0][t] = f2sum(a0);
            sc[1][t] = f2sum(a1);
        }

        float* ab = (out_attn ? out_attn : g_attn) + (size_t)task * UU * LL;

        #pragma unroll
        for (int p = 0; p < 2; p++) {
            const int r = r0 + p;
            const int ri = r / WS, rj = r % WS;   // bias row indexed by RANK (ref quirk)
            float mx = -FLT_MAX;
            #pragma unroll
            for (int t = 0; t < 3; t++) {
                int k = lane + t * 32;
                if (k < LL) {
                    int ki = k / WS, kj = k - ki * WS;
                    int bidx = (ri - ki + (WS - 1)) * (2 * WS - 1) + (rj - kj + (WS - 1));
                    sc[p][t] = (sc[p][t] + biass[bidx]) * scale;
                } else {
                    sc[p][t] = -FLT_MAX;
                }
                mx = fmaxf(mx, sc[p][t]);
            }
            #pragma unroll
            for (int o = 16; o > 0; o >>= 1)
                mx = fmaxf(mx, __shfl_xor_sync(0xffffffffu, mx, o));

            float sum = 0.0f;
            #pragma unroll
            for (int t = 0; t < 3; t++) {
                int k = lane + t * 32;
                sc[p][t] = (k < LL) ? __expf(sc[p][t] - mx) : 0.0f;
                sum += sc[p][t];
            }
            #pragma unroll
            for (int o = 16; o > 0; o >>= 1)
                sum += __shfl_xor_sync(0xffffffffu, sum, o);
            const float inv = 1.0f / sum;

            float* ao = ab + (size_t)r * LL;
            #pragma unroll
            for (int t = 0; t < 3; t++) {
                int k = lane + t * 32;
                if (k < LL) ao[k] = sc[p][t] * inv;
            }
        }
    }
}

// ============================================================================
// Kernel 2: per-(b,h) context = cumsum(V) with top rows replaced by attn @ V.
// 64 threads, thread = d. V streamed from gmem with batched loads (MLP=9).
// ============================================================================
__global__ __launch_bounds__(64, 16)
void pa_context_kernel(const float* __restrict__ v_in,
                       const float* __restrict__ attn_in,
                       float* __restrict__ out_ctx)
{
    __shared__ float attn_s[UU * LL];
    __shared__ int   topi_s[UU];
    __shared__ int   rank_s[LL];

    const int task = blockIdx.x;
    const int d = threadIdx.x;

    const float* ap = (attn_in ? attn_in : g_attn) + (size_t)task * UU * LL;
    for (int i = d; i < UU * LL; i += 64) attn_s[i] = ap[i];
    if (d < UU) topi_s[d] = g_topi[task * UU + d];
    for (int l = d; l < LL; l += 64) rank_s[l] = -1;
    __syncthreads();
    if (d < UU) rank_s[topi_s[d]] = d;
    __syncthreads();

    const int b = task >> 3;
    const int h = task & 7;
    const size_t base = ((size_t)b * LL * HH + h) * DD + d;
    const float* vb = v_in + base;
    float* ob = out_ctx + base;

    float upd[UU];
    #pragma unroll
    for (int r = 0; r < UU; r++) upd[r] = 0.0f;
    float cum = 0.0f;

    // 9 batches of 9: issue 9 independent LDGs before consuming (MLP = 9)
    for (int g = 0; g < 9; g++) {
        float vv[9];
        #pragma unroll
        for (int j = 0; j < 9; j++)
            vv[j] = __ldg(vb + (size_t)(g * 9 + j) * (HH * DD));
        #pragma unroll
        for (int j = 0; j < 9; j++) {
            const int l = g * 9 + j;
            cum += vv[j];
            if (rank_s[l] < 0) ob[(size_t)l * (HH * DD)] = cum;
            #pragma unroll
            for (int r = 0; r < UU; r++)
                upd[r] += attn_s[r * LL + l] * vv[j];
        }
    }

    #pragma unroll
    for (int r = 0; r < UU; r++)
        ob[(size_t)topi_s[r] * (HH * DD)] = upd[r];
}

extern "C" void kernel_launch(void* const* d_in, const int* in_sizes, int n_in,
                              void* d_out, int out_size)
{
    const float* q    = (const float*)d_in[0];
    const float* k    = (const float*)d_in[1];
    const float* v    = (const float*)d_in[2];
    const float* bias = (const float*)d_in[3];
    float* out = (float*)d_out;

    const long long ctx_elems  = (long long)BB * LL * HH * DD;
    const long long attn_elems = (long long)BB * HH * UU * LL;
    float* attn_out = ((long long)out_size >= ctx_elems + attn_elems)
                        ? out + ctx_elems : (float*)0;

    cudaFuncSetAttribute(pa_select_kernel,
                         cudaFuncAttributeMaxDynamicSharedMemorySize, SM1_BYTES);
    pa_select_kernel<<<BB * HH, NT1, SM1_BYTES>>>(q, k, bias, attn_out);
    pa_context_kernel<<<BB * HH, 64>>>(v, attn_out, out);
}